// round 4
// baseline (speedup 1.0000x reference)
#include <cuda_runtime.h>
#include <cuda_bf16.h>
#include <cstdint>

#define NB 32
#define NCC 32
#define NN 500
#define JD 53248            // NB*NCC*52
#define CT 1664             // NCC*52
#define NK 52
#define CNT 832000.0f
#define SOFF 26624000
#define MALPHA 0.05f
#define MEPS 1e-5f

// ---- device scratch (no allocations allowed) ----
__device__ __align__(16) __nv_bfloat16 g_A1[512 * 512];
__device__ __align__(16) __nv_bfloat16 g_A2[512 * 512];
__device__ __align__(16) float         g_h [NN * JD];
__device__ __align__(16) __nv_bfloat16 g_hb[NN * JD];
__device__ __align__(16) __nv_bfloat16 g_z1[NN * JD];
__device__ __align__(16) __nv_bfloat16 g_z2[NN * JD];
__device__ __align__(16) __nv_bfloat16 g_y1[NN * JD];
__device__ __align__(16) __nv_bfloat16 g_y2[NN * JD];
__device__ float g_W[5 * 1024 + 32];
__device__ float g_stats[64];

__device__ __forceinline__ float fast_tanh(float v) {
    float r; asm("tanh.approx.f32 %0, %1;" : "=f"(r) : "f"(v)); return r;
}
__device__ __forceinline__ float fast_sig(float v) {
    float e; asm("ex2.approx.f32 %0, %1;" : "=f"(e) : "f"(-v * 1.4426950408889634f));
    float r; asm("rcp.approx.f32 %0, %1;" : "=f"(r) : "f"(1.0f + e)); return r;
}

// ---- K1: normalized adjacencies (bf16, zero-padded to 512) + zero stats ----
__global__ void prep_adj(const float* __restrict__ adp) {
    int v = blockIdx.x, tid = threadIdx.x;
    __shared__ float rA[256], rB[256];
    float rs = 0.f, cs = 0.f;
    if (v < NN)
        for (int w = tid; w < NN; w += 256) { rs += adp[v * NN + w]; cs += adp[w * NN + v]; }
    rA[tid] = rs; rB[tid] = cs; __syncthreads();
    for (int s = 128; s > 0; s >>= 1) {
        if (tid < s) { rA[tid] += rA[tid + s]; rB[tid] += rB[tid + s]; }
        __syncthreads();
    }
    float i1 = 1.0f / (rA[0] + 1.0f), i2 = 1.0f / (rB[0] + 1.0f);
    for (int w = tid; w < 512; w += 256) {
        float a1 = 0.f, a2 = 0.f;
        if (v < NN && w < NN) {
            float d = (w == v) ? 1.0f : 0.0f;
            a1 = (adp[v * NN + w] + d) * i1;
            a2 = (adp[w * NN + v] + d) * i2;
        }
        g_A1[v * 512 + w] = __float2bfloat16(a1);
        g_A2[v * 512 + w] = __float2bfloat16(a2);
    }
    if (blockIdx.x == 0 && tid < 64) g_stats[tid] = 0.f;
}

// ---- K2: fold mixprop 1x1 weights ----
// out = [W0+a(W1+W2)]h + (1-a)[W1+aW2](Ah) + (1-a)^2 W2 (A^2 h)   (per adjacency)
__global__ void prep_w(const float* __restrict__ g1w, const float* __restrict__ g1b,
                       const float* __restrict__ g2w, const float* __restrict__ g2b) {
    int tid = threadIdx.x;
    const float A = MALPHA, O = 1.0f - MALPHA;
    for (int e = tid; e < 1024; e += blockDim.x) {
        int c = e >> 5, ci = e & 31;
        float a0 = g1w[c * 96 + ci], a1 = g1w[c * 96 + 32 + ci], a2 = g1w[c * 96 + 64 + ci];
        float b0 = g2w[c * 96 + ci], b1 = g2w[c * 96 + 32 + ci], b2 = g2w[c * 96 + 64 + ci];
        g_W[e]        = a0 + A * (a1 + a2) + b0 + A * (b1 + b2);
        g_W[1024 + e] = O * (a1 + A * a2);
        g_W[2048 + e] = O * O * a2;
        g_W[3072 + e] = O * (b1 + A * b2);
        g_W[4096 + e] = O * O * b2;
    }
    if (tid < 32) g_W[5120 + tid] = g1b[tid] + g2b[tid];
}

// ---- K3: dilated inception + gate -> h ----
template <int KT>
__device__ __forceinline__ void dob(const float* __restrict__ xs,
                                    const float* __restrict__ fw,
                                    const float* __restrict__ gw,
                                    int t0, float* fa, float* ga) {
    const int TS = 12 - 2 * (KT - 1);
    for (int ci = 0; ci < 32; ci++) {
        float xv[16];
#pragma unroll
        for (int q = 0; q < 8; q++)
            *(float2*)&xv[2 * q] = *(const float2*)&xs[ci * 64 + t0 + 2 * q];
#pragma unroll
        for (int j = 0; j < KT; j++) {
            float wf = fw[ci * KT + j], wg = gw[ci * KT + j];
#pragma unroll
            for (int tt = 0; tt < 4; tt++) {
                float xq = xv[TS + 2 * j + tt];
                fa[tt] = fmaf(wf, xq, fa[tt]);
                ga[tt] = fmaf(wg, xq, ga[tt]);
            }
        }
    }
}

__global__ __launch_bounds__(416) void inception(
    const float* __restrict__ x,
    const float* __restrict__ fw2, const float* __restrict__ fb2,
    const float* __restrict__ fw3, const float* __restrict__ fb3,
    const float* __restrict__ fw6, const float* __restrict__ fb6,
    const float* __restrict__ fw7, const float* __restrict__ fb7,
    const float* __restrict__ gw2, const float* __restrict__ gb2,
    const float* __restrict__ gw3, const float* __restrict__ gb3,
    const float* __restrict__ gw6, const float* __restrict__ gb6,
    const float* __restrict__ gw7, const float* __restrict__ gb7) {
    __shared__ float xs[2048];
    __shared__ float ws[9216];
    __shared__ float bsm[64];
    int n = blockIdx.x, b = blockIdx.y, tid = threadIdx.x;

    const float* xb = x + (size_t)b * (32 * NN * 64) + n * 64;
    for (int v = tid; v < 512; v += 416) {
        int ci = v >> 4, tq = v & 15;
        *(float4*)&xs[ci * 64 + tq * 4] = *(const float4*)&xb[(size_t)ci * (NN * 64) + tq * 4];
    }
    {
        const float* wp[8] = {fw2, fw3, fw6, fw7, gw2, gw3, gw6, gw7};
        const int wsz[8] = {512, 768, 1536, 1792, 512, 768, 1536, 1792};
        const int wof[8] = {0, 512, 1280, 2816, 4608, 5120, 5888, 7424};
        for (int a = 0; a < 8; a++)
            for (int v = tid; v < wsz[a]; v += 416) ws[wof[a] + v] = wp[a][v];
    }
    if (tid < 64) {
        const float* bp[8] = {fb2, fb3, fb6, fb7, gb2, gb3, gb6, gb7};
        bsm[tid] = bp[tid >> 3][tid & 7];
    }
    __syncthreads();

    int c = tid / 13, tg = tid % 13, t0 = tg * 4;
    int br = c >> 3, cc = c & 7;
    float fa[4] = {0.f, 0.f, 0.f, 0.f}, ga[4] = {0.f, 0.f, 0.f, 0.f};
    switch (br) {
        case 0: dob<2>(xs, ws + 0    + cc * 64,  ws + 4608 + cc * 64,         t0, fa, ga); break;
        case 1: dob<3>(xs, ws + 512  + cc * 96,  ws + 4608 + 512 + cc * 96,   t0, fa, ga); break;
        case 2: dob<6>(xs, ws + 1280 + cc * 192, ws + 4608 + 1280 + cc * 192, t0, fa, ga); break;
        default: dob<7>(xs, ws + 2816 + cc * 224, ws + 4608 + 2816 + cc * 224, t0, fa, ga); break;
    }
    float fb = bsm[br * 8 + cc], gb = bsm[32 + br * 8 + cc];
    size_t base = (size_t)n * JD + (b * 32 + c) * NK + t0;
#pragma unroll
    for (int tt = 0; tt < 4; tt++) {
        float hv = fast_tanh(fa[tt] + fb) * fast_sig(ga[tt] + gb);
        g_h[base + tt] = hv;
        g_hb[base + tt] = __float2bfloat16(hv);
    }
}

// ---- K4: node-dim GEMM (bf16 mma, fp32 accum) ----
__device__ __forceinline__ void mma_bf16(float* c, const uint32_t* a, const uint32_t* b) {
    asm volatile(
        "mma.sync.aligned.m16n8k16.row.col.f32.bf16.bf16.f32 "
        "{%0,%1,%2,%3}, {%4,%5,%6,%7}, {%8,%9}, {%0,%1,%2,%3};"
        : "+f"(c[0]), "+f"(c[1]), "+f"(c[2]), "+f"(c[3])
        : "r"(a[0]), "r"(a[1]), "r"(a[2]), "r"(a[3]), "r"(b[0]), "r"(b[1]));
}

__global__ __launch_bounds__(128) void node_gemm(int mode) {
    const int nt = blockIdx.x, mt = blockIdx.y, bz = blockIdx.z;
    const __nv_bfloat16* Am = bz ? g_A2 : g_A1;
    const __nv_bfloat16* Bm;
    __nv_bfloat16* Dm;
    if (mode == 0) { Bm = g_hb;             Dm = bz ? g_y1 : g_z1; }
    else           { Bm = bz ? g_y1 : g_z1; Dm = bz ? g_y2 : g_z2; }

    __shared__ __align__(16) __nv_bfloat16 As[64 * 40];
    __shared__ __align__(16) __nv_bfloat16 Bs[64 * 42];  // [n][k]
    int tid = threadIdx.x, lane = tid & 31, wid = tid >> 5;
    int wr = wid >> 1, wc = wid & 1;
    int lr = lane >> 2, lc2 = (lane & 3) * 2;

    float acc[2][4][4];
#pragma unroll
    for (int mi = 0; mi < 2; mi++)
#pragma unroll
        for (int ni = 0; ni < 4; ni++)
#pragma unroll
            for (int q = 0; q < 4; q++) acc[mi][ni][q] = 0.f;

    for (int kt = 0; kt < 16; kt++) {
#pragma unroll
        for (int i = 0; i < 4; i++) {
            int v = tid + i * 128;
            int r = v >> 3, cq = v & 7;
            *(uint2*)&As[r * 40 + cq * 4] =
                *(const uint2*)&Am[(mt * 64 + r) * 512 + kt * 32 + cq * 4];
        }
#pragma unroll
        for (int i = 0; i < 4; i++) {
            int v = tid + i * 128;
            int r = v >> 4, jq = v & 15;
            int w = kt * 32 + r;
            uint2 d = make_uint2(0u, 0u);
            if (w < NN) d = *(const uint2*)&Bm[(size_t)w * JD + nt * 64 + jq * 4];
            __nv_bfloat16 e[4];
            *(uint2*)e = d;
#pragma unroll
            for (int q = 0; q < 4; q++) Bs[(jq * 4 + q) * 42 + r] = e[q];
        }
        __syncthreads();
#pragma unroll
        for (int kk = 0; kk < 2; kk++) {
            uint32_t a[2][4], bf[4][2];
#pragma unroll
            for (int mi = 0; mi < 2; mi++) {
                int row = wr * 32 + mi * 16 + lr;
                a[mi][0] = *(const uint32_t*)&As[row * 40 + kk * 16 + lc2];
                a[mi][1] = *(const uint32_t*)&As[(row + 8) * 40 + kk * 16 + lc2];
                a[mi][2] = *(const uint32_t*)&As[row * 40 + kk * 16 + lc2 + 8];
                a[mi][3] = *(const uint32_t*)&As[(row + 8) * 40 + kk * 16 + lc2 + 8];
            }
#pragma unroll
            for (int ni = 0; ni < 4; ni++) {
                int nrow = wc * 32 + ni * 8 + lr;
                bf[ni][0] = *(const uint32_t*)&Bs[nrow * 42 + kk * 16 + lc2];
                bf[ni][1] = *(const uint32_t*)&Bs[nrow * 42 + kk * 16 + lc2 + 8];
            }
#pragma unroll
            for (int mi = 0; mi < 2; mi++)
#pragma unroll
                for (int ni = 0; ni < 4; ni++) mma_bf16(acc[mi][ni], a[mi], bf[ni]);
        }
        __syncthreads();
    }
#pragma unroll
    for (int mi = 0; mi < 2; mi++)
#pragma unroll
        for (int ni = 0; ni < 4; ni++) {
            int col = nt * 64 + wc * 32 + ni * 8 + lc2;
            int v0 = mt * 64 + wr * 32 + mi * 16 + lr;
            if (v0 < NN)
                *(__nv_bfloat162*)&Dm[(size_t)v0 * JD + col] =
                    __floats2bfloat162_rn(acc[mi][ni][0], acc[mi][ni][1]);
            if (v0 + 8 < NN)
                *(__nv_bfloat162*)&Dm[(size_t)(v0 + 8) * JD + col] =
                    __floats2bfloat162_rn(acc[mi][ni][2], acc[mi][ni][3]);
        }
}

// ---- K5: skip conv as fp32 GEMM ----
__global__ __launch_bounds__(128) void skip_gemm(const float* __restrict__ sw,
                                                 const float* __restrict__ sb,
                                                 float* __restrict__ out) {
    __shared__ float Hs[32 * 33];
    __shared__ float Ss[64 * 33];
    int tid = threadIdx.x;
    int tx = tid & 15, ty = tid >> 4;
    float acc[4][4];
#pragma unroll
    for (int a = 0; a < 4; a++)
#pragma unroll
        for (int q = 0; q < 4; q++) acc[a][q] = 0.f;
    int r0 = blockIdx.x * 32;
    for (int kt = 0; kt < 52; kt++) {
#pragma unroll
        for (int i = 0; i < 8; i++) {
            int v = tid + i * 128;
            Hs[(v >> 5) * 33 + (v & 31)] = g_h[(size_t)(r0 + (v >> 5)) * CT + kt * 32 + (v & 31)];
        }
#pragma unroll
        for (int i = 0; i < 16; i++) {
            int v = tid + i * 128;
            Ss[(v >> 5) * 33 + (v & 31)] = sw[(v >> 5) * CT + kt * 32 + (v & 31)];
        }
        __syncthreads();
#pragma unroll
        for (int kk = 0; kk < 32; kk++) {
            float hv[4], sv[4];
#pragma unroll
            for (int a = 0; a < 4; a++) hv[a] = Hs[(ty * 4 + a) * 33 + kk];
#pragma unroll
            for (int q = 0; q < 4; q++) sv[q] = Ss[(tx * 4 + q) * 33 + kk];
#pragma unroll
            for (int a = 0; a < 4; a++)
#pragma unroll
                for (int q = 0; q < 4; q++) acc[a][q] = fmaf(hv[a], sv[q], acc[a][q]);
        }
        __syncthreads();
    }
#pragma unroll
    for (int a = 0; a < 4; a++) {
        int r = r0 + ty * 4 + a;
        int n = r >> 5, b = r & 31;
#pragma unroll
        for (int q = 0; q < 4; q++) {
            int cs = tx * 4 + q;
            out[SOFF + b * 32000 + cs * 500 + n] = acc[a][q] + sb[cs];
        }
    }
}

// ---- K6: channel mix + residual -> xo (into d_out) + per-batch stats ----
__global__ __launch_bounds__(128) void combine(const float* __restrict__ x,
                                               float* __restrict__ out) {
    __shared__ float Wc[5120];
    __shared__ float bsm[32];
    __shared__ float hs[CT];
    __shared__ __nv_bfloat16 zs[4][CT];
    __shared__ float red[2][128];
    int n = blockIdx.x, b = blockIdx.y, tid = threadIdx.x;

    for (int v = tid; v < 5120; v += 128) Wc[v] = g_W[v];
    if (tid < 32) bsm[tid] = g_W[5120 + tid];
    size_t base = (size_t)n * JD + b * CT;
    for (int v = tid; v < CT; v += 128) {
        hs[v] = g_h[base + v];
        zs[0][v] = g_z1[base + v];
        zs[1][v] = g_z2[base + v];
        zs[2][v] = g_y1[base + v];
        zs[3][v] = g_y2[base + v];
    }
    __syncthreads();

    int cg = tid >> 4, tq = tid & 15, t0 = tq * 4;
    float acc[4][4] = {};
    float lsum = 0.f, lsq = 0.f;
    if (tq < 13) {
        for (int ci = 0; ci < 32; ci++) {
            float u0[4];
            *(float4*)u0 = *(const float4*)&hs[ci * NK + t0];
            float u[4][4];
#pragma unroll
            for (int s2 = 0; s2 < 4; s2++) {
                float2 f0 = __bfloat1622float2(*(const __nv_bfloat162*)&zs[s2][ci * NK + t0]);
                float2 f1 = __bfloat1622float2(*(const __nv_bfloat162*)&zs[s2][ci * NK + t0 + 2]);
                u[s2][0] = f0.x; u[s2][1] = f0.y; u[s2][2] = f1.x; u[s2][3] = f1.y;
            }
#pragma unroll
            for (int a = 0; a < 4; a++) {
                int c = cg * 4 + a;
                float w0 = Wc[c * 32 + ci], w1 = Wc[1024 + c * 32 + ci], w2 = Wc[2048 + c * 32 + ci];
                float w3 = Wc[3072 + c * 32 + ci], w4 = Wc[4096 + c * 32 + ci];
#pragma unroll
                for (int q = 0; q < 4; q++) {
                    float v = acc[a][q];
                    v = fmaf(w0, u0[q], v);
                    v = fmaf(w1, u[0][q], v);
                    v = fmaf(w2, u[1][q], v);
                    v = fmaf(w3, u[2][q], v);
                    v = fmaf(w4, u[3][q], v);
                    acc[a][q] = v;
                }
            }
        }
#pragma unroll
        for (int a = 0; a < 4; a++) {
            int c = cg * 4 + a;
            const float* resp = &x[((size_t)(b * 32 + c) * NN + n) * 64 + 12 + t0];
            float* op = &out[(size_t)b * 832000 + c * 26000 + n * NK + t0];
#pragma unroll
            for (int q = 0; q < 4; q++) {
                float v = acc[a][q] + bsm[c] + resp[q];
                op[q] = v;
                lsum += v;
                lsq += v * v;
            }
        }
    }
    red[0][tid] = lsum; red[1][tid] = lsq; __syncthreads();
    for (int s = 64; s > 0; s >>= 1) {
        if (tid < s) { red[0][tid] += red[0][tid + s]; red[1][tid] += red[1][tid + s]; }
        __syncthreads();
    }
    if (tid == 0) {
        atomicAdd(&g_stats[b], red[0][0]);
        atomicAdd(&g_stats[32 + b], red[1][0]);
    }
}

// ---- K7: layernorm apply (in place on d_out) ----
__global__ __launch_bounds__(256) void normalize(const int* __restrict__ idx,
                                                 const float* __restrict__ lw,
                                                 const float* __restrict__ lb,
                                                 float* __restrict__ out) {
    int i = blockIdx.x * 256 + threadIdx.x;
    int e = i * 4;
    int b = e / 832000;
    int r = e - b * 832000;
    int c = r / 26000;
    int r2 = r - c * 26000;
    int n = r2 / NK;
    int t = r2 - n * NK;
    float mu = g_stats[b] * (1.0f / CNT);
    float var = g_stats[32 + b] * (1.0f / CNT) - mu * mu;
    float inv = rsqrtf(var + MEPS);
    int ni = idx[n];
    int lo = c * 26000 + ni * NK + t;
    float4 v = *(float4*)&out[e];
    float4 w = *(const float4*)&lw[lo];
    float4 bb = *(const float4*)&lb[lo];
    v.x = (v.x - mu) * inv * w.x + bb.x;
    v.y = (v.y - mu) * inv * w.y + bb.y;
    v.z = (v.z - mu) * inv * w.z + bb.z;
    v.w = (v.w - mu) * inv * w.w + bb.w;
    *(float4*)&out[e] = v;
}

extern "C" void kernel_launch(void* const* d_in, const int* in_sizes, int n_in,
                              void* d_out, int out_size) {
    const float* x = (const float*)d_in[0];
    const int* idx;
    const float* adp;
    if (in_sizes[1] == NN) { idx = (const int*)d_in[1]; adp = (const float*)d_in[2]; }
    else                   { adp = (const float*)d_in[1]; idx = (const int*)d_in[2]; }
    const float* p[24];
    for (int i = 0; i < 24; i++) p[i] = (const float*)d_in[3 + i];
    // p: fw2,fb2,fw3,fb3,fw6,fb6,fw7,fb7,gw2,gb2,gw3,gb3,gw6,gb6,gw7,gb7,
    //    skip_w,skip_b,gc1_w,gc1_b,gc2_w,gc2_b,ln_w,ln_b
    float* out = (float*)d_out;

    prep_adj<<<512, 256>>>(adp);
    prep_w<<<1, 256>>>(p[18], p[19], p[20], p[21]);
    inception<<<dim3(NN, NB), 416>>>(x,
        p[0], p[1], p[2], p[3], p[4], p[5], p[6], p[7],
        p[8], p[9], p[10], p[11], p[12], p[13], p[14], p[15]);
    node_gemm<<<dim3(832, 8, 2), 128>>>(0);
    node_gemm<<<dim3(832, 8, 2), 128>>>(1);
    skip_gemm<<<500, 128>>>(p[16], p[17], out);
    combine<<<dim3(NN, NB), 128>>>(x, out);
    normalize<<<26000, 256>>>(idx, p[22], p[23], out);
}

// round 6
// speedup vs baseline: 1.3136x; 1.3136x over previous
#include <cuda_runtime.h>
#include <cuda_bf16.h>
#include <cstdint>

#define NB 32
#define NN 500
#define JD 53248            // NB*32*52
#define CT 1664             // 32*52
#define NK 52
#define CNT 832000.0f
#define SOFF 26624000
#define MALPHA 0.05f
#define MEPS 1e-5f

#define KPAD 40             // As row stride (bf16)
#define NPAD 136            // Bs row stride (bf16)

// ---- device scratch ----
__device__ __align__(16) __nv_bfloat16 g_A[4][512 * 512];   // A1, A1^2, A2, A2^2
__device__ __align__(16) float         g_h [NN * JD];
__device__ __align__(16) __nv_bfloat16 g_hb[NN * JD];
__device__ __align__(16) __nv_bfloat16 g_Z[4][NN * JD];     // A1h, A1^2h, A2h, A2^2h
__device__ float g_W[5 * 1024 + 32];
__device__ float g_stats[64];

__device__ __forceinline__ float fast_tanh(float v) {
    float r; asm("tanh.approx.f32 %0, %1;" : "=f"(r) : "f"(v)); return r;
}
__device__ __forceinline__ float fast_sig(float v) {
    float e; asm("ex2.approx.f32 %0, %1;" : "=f"(e) : "f"(-v * 1.4426950408889634f));
    float r; asm("rcp.approx.f32 %0, %1;" : "=f"(r) : "f"(1.0f + e)); return r;
}
__device__ __forceinline__ void cpa16(void* s, const void* g, int sz) {
    uint32_t sa = (uint32_t)__cvta_generic_to_shared(s);
    asm volatile("cp.async.cg.shared.global [%0], [%1], 16, %2;" :: "r"(sa), "l"(g), "r"(sz));
}
__device__ __forceinline__ void cp_commit() { asm volatile("cp.async.commit_group;"); }
template <int N> __device__ __forceinline__ void cp_wait() {
    asm volatile("cp.async.wait_group %0;" :: "n"(N));
}
__device__ __forceinline__ void ldsm4(uint32_t r[4], const void* p) {
    uint32_t a = (uint32_t)__cvta_generic_to_shared(p);
    asm volatile("ldmatrix.sync.aligned.m8n8.x4.shared.b16 {%0,%1,%2,%3}, [%4];"
        : "=r"(r[0]), "=r"(r[1]), "=r"(r[2]), "=r"(r[3]) : "r"(a));
}
__device__ __forceinline__ void ldsm4t(uint32_t r[4], const void* p) {
    uint32_t a = (uint32_t)__cvta_generic_to_shared(p);
    asm volatile("ldmatrix.sync.aligned.m8n8.x4.trans.shared.b16 {%0,%1,%2,%3}, [%4];"
        : "=r"(r[0]), "=r"(r[1]), "=r"(r[2]), "=r"(r[3]) : "r"(a));
}
__device__ __forceinline__ void mma_bf16(float* c, const uint32_t* a, const uint32_t* b) {
    asm volatile(
        "mma.sync.aligned.m16n8k16.row.col.f32.bf16.bf16.f32 "
        "{%0,%1,%2,%3}, {%4,%5,%6,%7}, {%8,%9}, {%0,%1,%2,%3};"
        : "+f"(c[0]), "+f"(c[1]), "+f"(c[2]), "+f"(c[3])
        : "r"(a[0]), "r"(a[1]), "r"(a[2]), "r"(a[3]), "r"(b[0]), "r"(b[1]));
}

// ---- K1: normalized adjacencies (bf16, zero-padded to 512) + zero stats ----
__global__ void prep_adj(const float* __restrict__ adp) {
    int v = blockIdx.x, tid = threadIdx.x;
    __shared__ float rA[256], rB[256];
    float rs = 0.f, cs = 0.f;
    if (v < NN)
        for (int w = tid; w < NN; w += 256) { rs += adp[v * NN + w]; cs += adp[w * NN + v]; }
    rA[tid] = rs; rB[tid] = cs; __syncthreads();
    for (int s = 128; s > 0; s >>= 1) {
        if (tid < s) { rA[tid] += rA[tid + s]; rB[tid] += rB[tid + s]; }
        __syncthreads();
    }
    float i1 = 1.0f / (rA[0] + 1.0f), i2 = 1.0f / (rB[0] + 1.0f);
    for (int w = tid; w < 512; w += 256) {
        float a1 = 0.f, a2 = 0.f;
        if (v < NN && w < NN) {
            float d = (w == v) ? 1.0f : 0.0f;
            a1 = (adp[v * NN + w] + d) * i1;
            a2 = (adp[w * NN + v] + d) * i2;
        }
        g_A[0][v * 512 + w] = __float2bfloat16(a1);
        g_A[2][v * 512 + w] = __float2bfloat16(a2);
    }
    if (blockIdx.x == 0 && tid < 64) g_stats[tid] = 0.f;
}

// ---- K2: fold mixprop 1x1 weights ----
__global__ void prep_w(const float* __restrict__ g1w, const float* __restrict__ g1b,
                       const float* __restrict__ g2w, const float* __restrict__ g2b) {
    int tid = threadIdx.x;
    const float A = MALPHA, O = 1.0f - MALPHA;
    for (int e = tid; e < 1024; e += blockDim.x) {
        int c = e >> 5, ci = e & 31;
        float a0 = g1w[c * 96 + ci], a1 = g1w[c * 96 + 32 + ci], a2 = g1w[c * 96 + 64 + ci];
        float b0 = g2w[c * 96 + ci], b1 = g2w[c * 96 + 32 + ci], b2 = g2w[c * 96 + 64 + ci];
        g_W[e]        = a0 + A * (a1 + a2) + b0 + A * (b1 + b2);
        g_W[1024 + e] = O * (a1 + A * a2);
        g_W[2048 + e] = O * O * a2;
        g_W[3072 + e] = O * (b1 + A * b2);
        g_W[4096 + e] = O * O * b2;
    }
    if (tid < 32) g_W[5120 + tid] = g1b[tid] + g2b[tid];
}

// ---- K3: square the adjacencies: g_A[1]=A1^2, g_A[3]=A2^2 ----
__global__ __launch_bounds__(256) void square_adj() {
    int src = blockIdx.z ? 2 : 0, dst = src + 1;
    __shared__ float Ls[64][33];
    __shared__ float Rs[32][65];
    int i0 = blockIdx.y * 64, j0 = blockIdx.x * 64;
    int tid = threadIdx.x, tx = tid & 15, ty = tid >> 4;
    float acc[4][4] = {};
    const __nv_bfloat16* Am = g_A[src];
    for (int kt = 0; kt < 16; kt++) {
#pragma unroll
        for (int q = 0; q < 8; q++) {
            int v = tid + q * 256;
            Ls[v >> 5][v & 31] = __bfloat162float(Am[(i0 + (v >> 5)) * 512 + kt * 32 + (v & 31)]);
        }
#pragma unroll
        for (int q = 0; q < 8; q++) {
            int v = tid + q * 256;
            Rs[v >> 6][v & 63] = __bfloat162float(Am[(kt * 32 + (v >> 6)) * 512 + j0 + (v & 63)]);
        }
        __syncthreads();
#pragma unroll
        for (int kk = 0; kk < 32; kk++) {
            float la[4], ra[4];
#pragma unroll
            for (int a = 0; a < 4; a++) la[a] = Ls[ty * 4 + a][kk];
#pragma unroll
            for (int q = 0; q < 4; q++) ra[q] = Rs[kk][tx * 4 + q];
#pragma unroll
            for (int a = 0; a < 4; a++)
#pragma unroll
                for (int q = 0; q < 4; q++) acc[a][q] = fmaf(la[a], ra[q], acc[a][q]);
        }
        __syncthreads();
    }
#pragma unroll
    for (int a = 0; a < 4; a++)
#pragma unroll
        for (int q = 0; q < 4; q++)
            g_A[dst][(i0 + ty * 4 + a) * 512 + j0 + tx * 4 + q] = __float2bfloat16(acc[a][q]);
}

// ---- K4: dilated inception + gate -> h ----
template <int KT>
__device__ __forceinline__ void dob2(const float* __restrict__ xrow,
                                     const float* __restrict__ fw,
                                     const float* __restrict__ gw,
                                     int t0, float fa[2][4], float ga[2][4]) {
    const int TS = 12 - 2 * (KT - 1);
    for (int ci = 0; ci < 32; ci++) {
        float xv[16];
#pragma unroll
        for (int q = 0; q < 8; q++)
            *(float2*)&xv[2 * q] = *(const float2*)&xrow[ci * 64 + t0 + 2 * q];
#pragma unroll
        for (int a = 0; a < 2; a++) {
#pragma unroll
            for (int j = 0; j < KT; j++) {
                float wf = fw[(a * 32 + ci) * KT + j];
                float wg = gw[(a * 32 + ci) * KT + j];
#pragma unroll
                for (int tt = 0; tt < 4; tt++) {
                    float xq = xv[TS + 2 * j + tt];
                    fa[a][tt] = fmaf(wf, xq, fa[a][tt]);
                    ga[a][tt] = fmaf(wg, xq, ga[a][tt]);
                }
            }
        }
    }
}

__global__ __launch_bounds__(208) void inception2(
    const float* __restrict__ x,
    const float* __restrict__ fw2, const float* __restrict__ fb2,
    const float* __restrict__ fw3, const float* __restrict__ fb3,
    const float* __restrict__ fw6, const float* __restrict__ fb6,
    const float* __restrict__ fw7, const float* __restrict__ fb7,
    const float* __restrict__ gw2, const float* __restrict__ gb2,
    const float* __restrict__ gw3, const float* __restrict__ gb3,
    const float* __restrict__ gw6, const float* __restrict__ gb6,
    const float* __restrict__ gw7, const float* __restrict__ gb7) {
    __shared__ float xs[2048];
    __shared__ float ws[9216];
    __shared__ float bsm[64];
    int n = blockIdx.x, b = blockIdx.y, tid = threadIdx.x;

    for (int v = tid; v < 512; v += 208) {
        int ci = v >> 4, tq = v & 15;
        *(float4*)&xs[ci * 64 + tq * 4] =
            *(const float4*)&x[(((size_t)b * 32 + ci) * NN + n) * 64 + tq * 4];
    }
    {
        const float* wp[8] = {fw2, fw3, fw6, fw7, gw2, gw3, gw6, gw7};
        const int wsz[8] = {512, 768, 1536, 1792, 512, 768, 1536, 1792};
        const int wof[8] = {0, 512, 1280, 2816, 4608, 5120, 5888, 7424};
        for (int a = 0; a < 8; a++)
            for (int v = tid; v < wsz[a]; v += 208) ws[wof[a] + v] = wp[a][v];
    }
    if (tid < 64) {
        const float* bp[8] = {fb2, fb3, fb6, fb7, gb2, gb3, gb6, gb7};
        bsm[tid] = bp[tid >> 3][tid & 7];
    }
    __syncthreads();

    int cg = tid / 13, tg = tid % 13, t0 = tg * 4;
    int br = cg >> 2, pair = cg & 3;
    float fa[2][4] = {}, ga[2][4] = {};
    switch (br) {
        case 0: dob2<2>(xs, ws + 0    + pair * 128, ws + 4608 + 0    + pair * 128, t0, fa, ga); break;
        case 1: dob2<3>(xs, ws + 512  + pair * 192, ws + 4608 + 512  + pair * 192, t0, fa, ga); break;
        case 2: dob2<6>(xs, ws + 1280 + pair * 384, ws + 4608 + 1280 + pair * 384, t0, fa, ga); break;
        default: dob2<7>(xs, ws + 2816 + pair * 448, ws + 4608 + 2816 + pair * 448, t0, fa, ga); break;
    }
#pragma unroll
    for (int a = 0; a < 2; a++) {
        int c = br * 8 + pair * 2 + a;
        float fb = bsm[c], gb = bsm[32 + c];
        size_t base = (size_t)n * JD + b * CT + c * NK + t0;
#pragma unroll
        for (int tt = 0; tt < 4; tt++) {
            float hv = fast_tanh(fa[a][tt] + fb) * fast_sig(ga[a][tt] + gb);
            g_h[base + tt] = hv;
            g_hb[base + tt] = __float2bfloat16(hv);
        }
    }
}

// ---- K5: node GEMMs — g_Z[z] = g_A[z] * g_hb, 4-way parallel ----
__global__ __launch_bounds__(256) void node_gemm2() {
    int nt = blockIdx.x, mt = blockIdx.y, za = blockIdx.z;
    const __nv_bfloat16* __restrict__ Am = g_A[za];
    const __nv_bfloat16* __restrict__ Bm = g_hb;
    __nv_bfloat16* __restrict__ Dm = g_Z[za];

    __shared__ __align__(16) __nv_bfloat16 As[2][64 * KPAD];
    __shared__ __align__(16) __nv_bfloat16 Bs[2][32 * NPAD];

    int tid = threadIdx.x, lane = tid & 31, wid = tid >> 5;
    int wm = wid >> 2, wn = wid & 3;

    int ar = tid >> 2, ac = (tid & 3) * 8;
    int b0r = tid >> 4, b0c = (tid & 15) * 8;
    int b1r = b0r + 16;

    float acc[2][4][4] = {};

    // stage 0 load
    {
        cpa16(&As[0][ar * KPAD + ac], Am + (mt * 64 + ar) * 512 + ac, 16);
        cpa16(&Bs[0][b0r * NPAD + b0c], Bm + (size_t)b0r * JD + nt * 128 + b0c, 16);
        cpa16(&Bs[0][b1r * NPAD + b0c], Bm + (size_t)b1r * JD + nt * 128 + b0c, 16);
        cp_commit();
    }

    for (int kt = 0; kt < 16; kt++) {
        int cur = kt & 1;
        if (kt < 15) {
            int nk = kt + 1;
            cpa16(&As[cur ^ 1][ar * KPAD + ac], Am + (mt * 64 + ar) * 512 + nk * 32 + ac, 16);
            int w0 = nk * 32 + b0r;
            cpa16(&Bs[cur ^ 1][b0r * NPAD + b0c],
                  Bm + (size_t)(w0 < NN ? w0 : 0) * JD + nt * 128 + b0c, w0 < NN ? 16 : 0);
            int w1 = nk * 32 + b1r;
            cpa16(&Bs[cur ^ 1][b1r * NPAD + b0c],
                  Bm + (size_t)(w1 < NN ? w1 : 0) * JD + nt * 128 + b0c, w1 < NN ? 16 : 0);
            cp_commit();
            cp_wait<1>();
        } else {
            cp_wait<0>();
        }
        __syncthreads();
#pragma unroll
        for (int kk = 0; kk < 2; kk++) {
            uint32_t af[2][4], bf[2][4];
#pragma unroll
            for (int mi = 0; mi < 2; mi++)
                ldsm4(af[mi],
                      &As[cur][(wm * 32 + mi * 16 + (lane & 15)) * KPAD + kk * 16 + (lane >> 4) * 8]);
#pragma unroll
            for (int nh = 0; nh < 2; nh++)
                ldsm4t(bf[nh],
                       &Bs[cur][(kk * 16 + (lane & 15)) * NPAD + wn * 32 + nh * 16 + (lane >> 4) * 8]);
#pragma unroll
            for (int mi = 0; mi < 2; mi++)
#pragma unroll
                for (int ni = 0; ni < 4; ni++) {
                    uint32_t bb[2] = {bf[ni >> 1][(ni & 1) * 2], bf[ni >> 1][(ni & 1) * 2 + 1]};
                    mma_bf16(acc[mi][ni], af[mi], bb);
                }
        }
        __syncthreads();
    }
#pragma unroll
    for (int mi = 0; mi < 2; mi++) {
        int r0 = mt * 64 + wm * 32 + mi * 16 + (lane >> 2);
#pragma unroll
        for (int ni = 0; ni < 4; ni++) {
            int col = nt * 128 + wn * 32 + ni * 8 + (lane & 3) * 2;
            if (r0 < NN)
                *(__nv_bfloat162*)&Dm[(size_t)r0 * JD + col] =
                    __floats2bfloat162_rn(acc[mi][ni][0], acc[mi][ni][1]);
            if (r0 + 8 < NN)
                *(__nv_bfloat162*)&Dm[(size_t)(r0 + 8) * JD + col] =
                    __floats2bfloat162_rn(acc[mi][ni][2], acc[mi][ni][3]);
        }
    }
}

// ---- K6: skip conv as fp32 GEMM ----
__global__ __launch_bounds__(128) void skip_gemm(const float* __restrict__ sw,
                                                 const float* __restrict__ sb,
                                                 float* __restrict__ out) {
    __shared__ float Hs[32 * 33];
    __shared__ float Ss[64 * 33];
    int tid = threadIdx.x;
    int tx = tid & 15, ty = tid >> 4;
    float acc[4][4] = {};
    int r0 = blockIdx.x * 32;
    for (int kt = 0; kt < 52; kt++) {
#pragma unroll
        for (int i = 0; i < 8; i++) {
            int v = tid + i * 128;
            Hs[(v >> 5) * 33 + (v & 31)] = g_h[(size_t)(r0 + (v >> 5)) * CT + kt * 32 + (v & 31)];
        }
#pragma unroll
        for (int i = 0; i < 16; i++) {
            int v = tid + i * 128;
            Ss[(v >> 5) * 33 + (v & 31)] = sw[(v >> 5) * CT + kt * 32 + (v & 31)];
        }
        __syncthreads();
#pragma unroll
        for (int kk = 0; kk < 32; kk++) {
            float hv[4], sv[4];
#pragma unroll
            for (int a = 0; a < 4; a++) hv[a] = Hs[(ty * 4 + a) * 33 + kk];
#pragma unroll
            for (int q = 0; q < 4; q++) sv[q] = Ss[(tx * 4 + q) * 33 + kk];
#pragma unroll
            for (int a = 0; a < 4; a++)
#pragma unroll
                for (int q = 0; q < 4; q++) acc[a][q] = fmaf(hv[a], sv[q], acc[a][q]);
        }
        __syncthreads();
    }
#pragma unroll
    for (int a = 0; a < 4; a++) {
        int r = r0 + ty * 4 + a;
        int n = r >> 5, b = r & 31;
#pragma unroll
        for (int q = 0; q < 4; q++) {
            int cs = tx * 4 + q;
            out[SOFF + b * 32000 + cs * 500 + n] = acc[a][q] + sb[cs];
        }
    }
}

// ---- K7: channel mix + residual -> xo + per-batch stats ----
__global__ __launch_bounds__(128) void combine(const float* __restrict__ x,
                                               float* __restrict__ out) {
    __shared__ float Wc[5120];
    __shared__ float bsm[32];
    __shared__ float hs[CT];
    __shared__ __nv_bfloat16 zs[4][CT];
    __shared__ float red[2][128];
    int n = blockIdx.x, b = blockIdx.y, tid = threadIdx.x;

    for (int v = tid; v < 5120; v += 128) Wc[v] = g_W[v];
    if (tid < 32) bsm[tid] = g_W[5120 + tid];
    size_t base = (size_t)n * JD + b * CT;
    for (int v = tid; v < CT; v += 128) {
        hs[v] = g_h[base + v];
        zs[0][v] = g_Z[0][base + v];
        zs[1][v] = g_Z[1][base + v];
        zs[2][v] = g_Z[2][base + v];
        zs[3][v] = g_Z[3][base + v];
    }
    __syncthreads();

    int cg = tid >> 4, tq = tid & 15, t0 = tq * 4;
    float acc[4][4] = {};
    float lsum = 0.f, lsq = 0.f;
    if (tq < 13) {
        for (int ci = 0; ci < 32; ci++) {
            float u0[4];
            *(float4*)u0 = *(const float4*)&hs[ci * NK + t0];
            float u[4][4];
#pragma unroll
            for (int s2 = 0; s2 < 4; s2++) {
                float2 f0 = __bfloat1622float2(*(const __nv_bfloat162*)&zs[s2][ci * NK + t0]);
                float2 f1 = __bfloat1622float2(*(const __nv_bfloat162*)&zs[s2][ci * NK + t0 + 2]);
                u[s2][0] = f0.x; u[s2][1] = f0.y; u[s2][2] = f1.x; u[s2][3] = f1.y;
            }
#pragma unroll
            for (int a = 0; a < 4; a++) {
                int c = cg * 4 + a;
                float w0 = Wc[c * 32 + ci], w1 = Wc[1024 + c * 32 + ci], w2 = Wc[2048 + c * 32 + ci];
                float w3 = Wc[3072 + c * 32 + ci], w4 = Wc[4096 + c * 32 + ci];
#pragma unroll
                for (int q = 0; q < 4; q++) {
                    float v = acc[a][q];
                    v = fmaf(w0, u0[q], v);
                    v = fmaf(w1, u[0][q], v);
                    v = fmaf(w2, u[1][q], v);
                    v = fmaf(w3, u[2][q], v);
                    v = fmaf(w4, u[3][q], v);
                    acc[a][q] = v;
                }
            }
        }
#pragma unroll
        for (int a = 0; a < 4; a++) {
            int c = cg * 4 + a;
            const float* resp = &x[((size_t)(b * 32 + c) * NN + n) * 64 + 12 + t0];
            float* op = &out[(size_t)b * 832000 + c * 26000 + n * NK + t0];
#pragma unroll
            for (int q = 0; q < 4; q++) {
                float v = acc[a][q] + bsm[c] + resp[q];
                op[q] = v;
                lsum += v;
                lsq += v * v;
            }
        }
    }
    red[0][tid] = lsum; red[1][tid] = lsq; __syncthreads();
    for (int s = 64; s > 0; s >>= 1) {
        if (tid < s) { red[0][tid] += red[0][tid + s]; red[1][tid] += red[1][tid + s]; }
        __syncthreads();
    }
    if (tid == 0) {
        atomicAdd(&g_stats[b], red[0][0]);
        atomicAdd(&g_stats[32 + b], red[1][0]);
    }
}

// ---- K8: layernorm apply ----
__global__ __launch_bounds__(256) void normalize(const int* __restrict__ idx,
                                                 const float* __restrict__ lw,
                                                 const float* __restrict__ lb,
                                                 float* __restrict__ out) {
    int i = blockIdx.x * 256 + threadIdx.x;
    int e = i * 4;
    int b = e / 832000;
    int r = e - b * 832000;
    int c = r / 26000;
    int r2 = r - c * 26000;
    int n = r2 / NK;
    int t = r2 - n * NK;
    float mu = g_stats[b] * (1.0f / CNT);
    float var = g_stats[32 + b] * (1.0f / CNT) - mu * mu;
    float inv = rsqrtf(var + MEPS);
    int ni = idx[n];
    int lo = c * 26000 + ni * NK + t;
    float4 v = *(float4*)&out[e];
    float4 w = *(const float4*)&lw[lo];
    float4 bb = *(const float4*)&lb[lo];
    v.x = (v.x - mu) * inv * w.x + bb.x;
    v.y = (v.y - mu) * inv * w.y + bb.y;
    v.z = (v.z - mu) * inv * w.z + bb.z;
    v.w = (v.w - mu) * inv * w.w + bb.w;
    *(float4*)&out[e] = v;
}

extern "C" void kernel_launch(void* const* d_in, const int* in_sizes, int n_in,
                              void* d_out, int out_size) {
    const float* x = (const float*)d_in[0];
    const int* idx;
    const float* adp;
    if (in_sizes[1] == NN) { idx = (const int*)d_in[1]; adp = (const float*)d_in[2]; }
    else                   { adp = (const float*)d_in[1]; idx = (const int*)d_in[2]; }
    const float* p[24];
    for (int i = 0; i < 24; i++) p[i] = (const float*)d_in[3 + i];
    float* out = (float*)d_out;

    prep_adj<<<512, 256>>>(adp);
    prep_w<<<1, 256>>>(p[18], p[19], p[20], p[21]);
    square_adj<<<dim3(8, 8, 2), 256>>>();
    inception2<<<dim3(NN, NB), 208>>>(x,
        p[0], p[1], p[2], p[3], p[4], p[5], p[6], p[7],
        p[8], p[9], p[10], p[11], p[12], p[13], p[14], p[15]);
    node_gemm2<<<dim3(416, 8, 4), 256>>>();
    skip_gemm<<<500, 128>>>(p[16], p[17], out);
    combine<<<dim3(NN, NB), 128>>>(x, out);
    normalize<<<26000, 256>>>(idx, p[22], p[23], out);
}